// round 1
// baseline (speedup 1.0000x reference)
#include <cuda_runtime.h>
#include <math.h>

#define NN 20000
#define EE 640000
#define HH 4
#define CC 64
#define FDIM 256   // HH*CC

// ---------------- scratch (device globals; no allocation allowed) ----------
__device__ float g_xh[NN * FDIM];   // current layer transformed features
__device__ float g_h1[NN * FDIM];   // layer-1 output (input to layer 2)
__device__ float g_as[NN * HH];
__device__ float g_ad[NN * HH];
__device__ float g_alpha[EE * HH];  // pre-softmax (post leaky-relu) logits
__device__ float g_coeff[EE * HH];  // normalized alpha * edge_atten
__device__ float g_amax[NN * HH];
__device__ float g_den[NN * HH];
__device__ float g_aek[HH];
__device__ int   g_deg[NN];
__device__ int   g_rowptr[NN + 1];
__device__ int   g_cursor[NN];
__device__ int   g_eid[EE];

// ---------------- CSR build -------------------------------------------------
__global__ void k_zero()
{
    int i = blockIdx.x * blockDim.x + threadIdx.x;
    if (i < NN) { g_deg[i] = 0; g_cursor[i] = 0; }
}

__global__ void k_deg(const int* __restrict__ dst)
{
    int e = blockIdx.x * blockDim.x + threadIdx.x;
    if (e < EE) atomicAdd(&g_deg[dst[e]], 1);
}

// single-block exclusive scan over g_deg -> g_rowptr
__global__ void k_scan()
{
    __shared__ int s[1024];
    int t = threadIdx.x;
    const int CH = (NN + 1023) / 1024;  // 20
    int base = t * CH;
    int sum = 0;
    for (int i = 0; i < CH; i++) {
        int idx = base + i;
        if (idx < NN) sum += g_deg[idx];
    }
    s[t] = sum;
    __syncthreads();
    for (int off = 1; off < 1024; off <<= 1) {
        int v = (t >= off) ? s[t - off] : 0;
        __syncthreads();
        s[t] += v;
        __syncthreads();
    }
    int run = s[t] - sum;  // exclusive prefix of this chunk
    for (int i = 0; i < CH; i++) {
        int idx = base + i;
        if (idx < NN) { g_rowptr[idx] = run; run += g_deg[idx]; }
    }
    if (t == 1023) g_rowptr[NN] = s[1023];
}

__global__ void k_fill(const int* __restrict__ dst)
{
    int e = blockIdx.x * blockDim.x + threadIdx.x;
    if (e >= EE) return;
    int d = dst[e];
    int pos = atomicAdd(&g_cursor[d], 1);
    g_eid[g_rowptr[d] + pos] = e;
}

// ---------------- GEMM: C[M,256] = A[M,K] @ B[K,256] ------------------------
__global__ void k_gemm(const float* __restrict__ A, const float* __restrict__ B,
                       float* __restrict__ C, int M, int K)
{
    const int BM = 64, BN = 64, BK = 16;
    __shared__ float As[BK][BM];
    __shared__ float Bs[BK][BN];
    int tid = threadIdx.x;               // 256 threads
    int tx = tid & 15, ty = tid >> 4;    // 16x16 threads, 4x4 micro-tile
    int row0 = blockIdx.y * BM;
    int col0 = blockIdx.x * BN;

    int ar  = tid >> 2;   // 0..63 : row in A tile
    int ac4 = tid & 3;    // 0..3  : float4 column
    int br  = tid >> 4;   // 0..15 : k row in B tile
    int bc4 = tid & 15;   // 0..15 : float4 column

    float acc[4][4];
#pragma unroll
    for (int i = 0; i < 4; i++)
#pragma unroll
        for (int j = 0; j < 4; j++) acc[i][j] = 0.f;

    for (int k0 = 0; k0 < K; k0 += BK) {
        float4 av = make_float4(0.f, 0.f, 0.f, 0.f);
        int arow = row0 + ar;
        if (arow < M)
            av = *(const float4*)&A[(long)arow * K + k0 + ac4 * 4];
        As[ac4 * 4 + 0][ar] = av.x;
        As[ac4 * 4 + 1][ar] = av.y;
        As[ac4 * 4 + 2][ar] = av.z;
        As[ac4 * 4 + 3][ar] = av.w;
        float4 bv = *(const float4*)&B[(long)(k0 + br) * 256 + col0 + bc4 * 4];
        *(float4*)&Bs[br][bc4 * 4] = bv;
        __syncthreads();
#pragma unroll
        for (int k = 0; k < BK; k++) {
            float ra[4], rb[4];
#pragma unroll
            for (int i = 0; i < 4; i++) ra[i] = As[k][ty * 4 + i];
#pragma unroll
            for (int j = 0; j < 4; j++) rb[j] = Bs[k][tx * 4 + j];
#pragma unroll
            for (int i = 0; i < 4; i++)
#pragma unroll
                for (int j = 0; j < 4; j++) acc[i][j] += ra[i] * rb[j];
        }
        __syncthreads();
    }
#pragma unroll
    for (int i = 0; i < 4; i++) {
        int r = row0 + ty * 4 + i;
        if (r < M) {
            float4 v = make_float4(acc[i][0], acc[i][1], acc[i][2], acc[i][3]);
            *(float4*)&C[(long)r * 256 + col0 + tx * 4] = v;
        }
    }
}

// ---------------- alpha_src / alpha_dst per node ----------------------------
__global__ void k_asad(const float* __restrict__ xh,
                       const float* __restrict__ a_src,
                       const float* __restrict__ a_dst)
{
    int n = blockIdx.x;
    int t = threadIdx.x;  // 256
    float v = xh[n * FDIM + t];
    float ps = v * a_src[t];
    float pd = v * a_dst[t];
#pragma unroll
    for (int off = 16; off > 0; off >>= 1) {
        ps += __shfl_down_sync(0xffffffffu, ps, off);
        pd += __shfl_down_sync(0xffffffffu, pd, off);
    }
    __shared__ float ss[8], sd[8];
    int w = t >> 5, lane = t & 31;
    if (lane == 0) { ss[w] = ps; sd[w] = pd; }
    __syncthreads();
    if (t < HH) {
        g_as[n * HH + t] = ss[2 * t] + ss[2 * t + 1];
        g_ad[n * HH + t] = sd[2 * t] + sd[2 * t + 1];
    }
}

// K_h = sum_c W_e[0,h*C+c] * a_e[h,c]
__global__ void k_aek(const float* __restrict__ We, const float* __restrict__ ae)
{
    int t = threadIdx.x;  // 256
    float p = We[t] * ae[t];
#pragma unroll
    for (int off = 16; off > 0; off >>= 1)
        p += __shfl_down_sync(0xffffffffu, p, off);
    __shared__ float sh[8];
    int w = t >> 5, lane = t & 31;
    if (lane == 0) sh[w] = p;
    __syncthreads();
    if (t < HH) g_aek[t] = sh[2 * t] + sh[2 * t + 1];
}

// ---------------- per-edge logits ------------------------------------------
__device__ __forceinline__ float lrelu(float x) { return x > 0.f ? x : 0.2f * x; }

__global__ void k_alpha(const int* __restrict__ src, const int* __restrict__ dst,
                        const float* __restrict__ eattr)
{
    int e = blockIdx.x * blockDim.x + threadIdx.x;
    if (e >= EE) return;
    int s = src[e], d = dst[e];
    float ea = eattr[e];
    float4 as = *(const float4*)&g_as[s * 4];
    float4 ad = *(const float4*)&g_ad[d * 4];
    float4 ak = *(const float4*)g_aek;
    float4 a;
    a.x = lrelu(as.x + ad.x + ak.x * ea);
    a.y = lrelu(as.y + ad.y + ak.y * ea);
    a.z = lrelu(as.z + ad.z + ak.z * ea);
    a.w = lrelu(as.w + ad.w + ak.w * ea);
    *(float4*)&g_alpha[e * 4] = a;
}

// ---------------- per-node segment max + sum(exp) (warp per node) ----------
__global__ void k_softmax()
{
    int warp = threadIdx.x >> 5;
    int lane = threadIdx.x & 31;
    int n = blockIdx.x * 4 + warp;
    if (n >= NN) return;
    int lo = g_rowptr[n], hi = g_rowptr[n + 1];
    float4 m = make_float4(-INFINITY, -INFINITY, -INFINITY, -INFINITY);
    for (int i = lo + lane; i < hi; i += 32) {
        int e = g_eid[i];
        float4 a = *(const float4*)&g_alpha[e * 4];
        m.x = fmaxf(m.x, a.x); m.y = fmaxf(m.y, a.y);
        m.z = fmaxf(m.z, a.z); m.w = fmaxf(m.w, a.w);
    }
#pragma unroll
    for (int off = 16; off > 0; off >>= 1) {
        m.x = fmaxf(m.x, __shfl_xor_sync(0xffffffffu, m.x, off));
        m.y = fmaxf(m.y, __shfl_xor_sync(0xffffffffu, m.y, off));
        m.z = fmaxf(m.z, __shfl_xor_sync(0xffffffffu, m.z, off));
        m.w = fmaxf(m.w, __shfl_xor_sync(0xffffffffu, m.w, off));
    }
    float4 s4 = make_float4(0.f, 0.f, 0.f, 0.f);
    for (int i = lo + lane; i < hi; i += 32) {
        int e = g_eid[i];
        float4 a = *(const float4*)&g_alpha[e * 4];
        s4.x += expf(a.x - m.x); s4.y += expf(a.y - m.y);
        s4.z += expf(a.z - m.z); s4.w += expf(a.w - m.w);
    }
#pragma unroll
    for (int off = 16; off > 0; off >>= 1) {
        s4.x += __shfl_xor_sync(0xffffffffu, s4.x, off);
        s4.y += __shfl_xor_sync(0xffffffffu, s4.y, off);
        s4.z += __shfl_xor_sync(0xffffffffu, s4.z, off);
        s4.w += __shfl_xor_sync(0xffffffffu, s4.w, off);
    }
    if (lane == 0) {
        *(float4*)&g_amax[n * 4] = m;
        *(float4*)&g_den[n * 4] = s4;
    }
}

// ---------------- per-edge normalize; emit attention + coeff ----------------
__global__ void k_norm(const int* __restrict__ dst, const float* __restrict__ eatten,
                       float* __restrict__ w_out)
{
    int e = blockIdx.x * blockDim.x + threadIdx.x;
    if (e >= EE) return;
    int d = dst[e];
    float4 a = *(const float4*)&g_alpha[e * 4];
    float4 m = *(const float4*)&g_amax[d * 4];
    float4 dn = *(const float4*)&g_den[d * 4];
    float at = eatten[e];
    float4 w;
    w.x = expf(a.x - m.x) / (dn.x + 1e-16f);
    w.y = expf(a.y - m.y) / (dn.y + 1e-16f);
    w.z = expf(a.z - m.z) / (dn.z + 1e-16f);
    w.w = expf(a.w - m.w) / (dn.w + 1e-16f);
    *(float4*)&w_out[e * 4] = w;
    float4 c = make_float4(w.x * at, w.y * at, w.z * at, w.w * at);
    *(float4*)&g_coeff[e * 4] = c;
}

// ---------------- per-node message aggregation (block per node) -------------
__global__ void k_agg(const int* __restrict__ src, const float* __restrict__ xh,
                      const float* __restrict__ bias, float* __restrict__ out)
{
    int n = blockIdx.x;
    int t = threadIdx.x;     // 256
    int h = t >> 6;
    int lo = g_rowptr[n], hi = g_rowptr[n + 1];
    float acc = 0.f;
    __shared__ int   s_src[64];
    __shared__ float s_c[64][4];
    for (int base = lo; base < hi; base += 64) {
        int cnt = min(64, hi - base);
        if (t < cnt) {
            int e = g_eid[base + t];
            s_src[t] = src[e];
            float4 cc = *(const float4*)&g_coeff[e * 4];
            s_c[t][0] = cc.x; s_c[t][1] = cc.y; s_c[t][2] = cc.z; s_c[t][3] = cc.w;
        }
        __syncthreads();
        for (int i = 0; i < cnt; i++) {
            acc += xh[(long)s_src[i] * FDIM + t] * s_c[i][h];
        }
        __syncthreads();
    }
    out[(long)n * FDIM + t] = acc + bias[t];
}

// ---------------- driver ----------------------------------------------------
extern "C" void kernel_launch(void* const* d_in, const int* in_sizes, int n_in,
                              void* d_out, int out_size)
{
    const float* x      = (const float*)d_in[0];
    const int*   ei     = (const int*)d_in[1];
    const float* eattr  = (const float*)d_in[3];
    const float* eatten = (const float*)d_in[4];
    const float* W1     = (const float*)d_in[5];
    const float* as1    = (const float*)d_in[6];
    const float* ad1    = (const float*)d_in[7];
    const float* We1    = (const float*)d_in[8];
    const float* ae1    = (const float*)d_in[9];
    const float* b1     = (const float*)d_in[10];
    const float* W2     = (const float*)d_in[11];
    const float* as2    = (const float*)d_in[12];
    const float* ad2    = (const float*)d_in[13];
    const float* We2    = (const float*)d_in[14];
    const float* ae2    = (const float*)d_in[15];
    const float* b2     = (const float*)d_in[16];

    const int* src = ei;
    const int* dst = ei + EE;

    float* out    = (float*)d_out;
    float* h_out  = out;
    float* w1_out = out + (long)NN * FDIM;
    float* w2_out = w1_out + (long)EE * HH;

    float* xh = nullptr; float* h1 = nullptr;
    cudaGetSymbolAddress((void**)&xh, g_xh);
    cudaGetSymbolAddress((void**)&h1, g_h1);

    const int EB = (EE + 255) / 256;

    // CSR by dst (shared by both layers)
    k_zero<<<(NN + 255) / 256, 256>>>();
    k_deg<<<EB, 256>>>(dst);
    k_scan<<<1, 1024>>>();
    k_fill<<<EB, 256>>>(dst);

    dim3 ggrid(4, (NN + 63) / 64);

    // ---- layer 1 ----
    k_gemm<<<ggrid, 256>>>(x, W1, xh, NN, 128);
    k_asad<<<NN, 256>>>(xh, as1, ad1);
    k_aek<<<1, 256>>>(We1, ae1);
    k_alpha<<<EB, 256>>>(src, dst, eattr);
    k_softmax<<<(NN + 3) / 4, 128>>>();
    k_norm<<<EB, 256>>>(dst, eatten, w1_out);
    k_agg<<<NN, 256>>>(src, xh, b1, h1);

    // ---- layer 2 ----
    k_gemm<<<ggrid, 256>>>(h1, W2, xh, NN, 256);
    k_asad<<<NN, 256>>>(xh, as2, ad2);
    k_aek<<<1, 256>>>(We2, ae2);
    k_alpha<<<EB, 256>>>(src, dst, eattr);
    k_softmax<<<(NN + 3) / 4, 128>>>();
    k_norm<<<EB, 256>>>(dst, eatten, w2_out);
    k_agg<<<NN, 256>>>(src, xh, b2, h_out);
}

// round 3
// speedup vs baseline: 1.0676x; 1.0676x over previous
#include <cuda_runtime.h>
#include <cuda_bf16.h>
#include <math.h>
#include <stdint.h>

#define NN 20000
#define NNPAD 20096          // 157 * 128
#define EE 640000
#define HH 4
#define CC 64
#define FDIM 256   // HH*CC

// ---------------- scratch (device globals; no allocation allowed) ----------
__device__ float g_xh[NN * FDIM];   // current layer transformed features
__device__ float g_h1[NN * FDIM];   // layer-1 output (input to layer 2)
__device__ float g_as[NN * HH];
__device__ float g_ad[NN * HH];
__device__ float g_alpha[EE * HH];  // pre-softmax (post leaky-relu) logits
__device__ float g_coeff[EE * HH];  // normalized alpha * edge_atten
__device__ float g_amax[NN * HH];
__device__ float g_den[NN * HH];
__device__ float g_aek[HH];
__device__ int   g_deg[NN];
__device__ int   g_rowptr[NN + 1];
__device__ int   g_cursor[NN];
__device__ int   g_eid[EE];
// split-bf16 operands: A' = [Ah|Ah|Al] (row-major, K'=3K), B' = [Bh;Bl;Bh] ([3K][256])
__device__ __nv_bfloat16 g_A3[(size_t)NNPAD * 768];
__device__ __nv_bfloat16 g_B3[768 * 256];

// ---------------- helpers ----------------------------------------------------
__device__ __forceinline__ uint32_t smem_u32(const void* p) {
    uint32_t a;
    asm("{ .reg .u64 t; cvta.to.shared.u64 t, %1; cvt.u32.u64 %0, t; }" : "=r"(a) : "l"(p));
    return a;
}
__device__ __forceinline__ void ldsm_x4(uint32_t addr, uint32_t& r0, uint32_t& r1,
                                        uint32_t& r2, uint32_t& r3) {
    asm volatile("ldmatrix.sync.aligned.m8n8.x4.shared.b16 {%0,%1,%2,%3}, [%4];"
                 : "=r"(r0), "=r"(r1), "=r"(r2), "=r"(r3) : "r"(addr));
}
__device__ __forceinline__ void ldsm_x4t(uint32_t addr, uint32_t& r0, uint32_t& r1,
                                         uint32_t& r2, uint32_t& r3) {
    asm volatile("ldmatrix.sync.aligned.m8n8.x4.trans.shared.b16 {%0,%1,%2,%3}, [%4];"
                 : "=r"(r0), "=r"(r1), "=r"(r2), "=r"(r3) : "r"(addr));
}
__device__ __forceinline__ void mma16816(float* d, const uint32_t* a, uint32_t b0, uint32_t b1) {
    asm volatile(
        "mma.sync.aligned.m16n8k16.row.col.f32.bf16.bf16.f32 "
        "{%0,%1,%2,%3}, {%4,%5,%6,%7}, {%8,%9}, {%0,%1,%2,%3};"
        : "+f"(d[0]), "+f"(d[1]), "+f"(d[2]), "+f"(d[3])
        : "r"(a[0]), "r"(a[1]), "r"(a[2]), "r"(a[3]), "r"(b0), "r"(b1));
}

// ---------------- CSR build -------------------------------------------------
__global__ void k_zero()
{
    int i = blockIdx.x * blockDim.x + threadIdx.x;
    if (i < NN) { g_deg[i] = 0; g_cursor[i] = 0; }
}

__global__ void k_deg(const int* __restrict__ dst)
{
    int e = blockIdx.x * blockDim.x + threadIdx.x;
    if (e < EE) atomicAdd(&g_deg[dst[e]], 1);
}

__global__ void k_scan()
{
    __shared__ int s[1024];
    int t = threadIdx.x;
    const int CH = (NN + 1023) / 1024;
    int base = t * CH;
    int sum = 0;
    for (int i = 0; i < CH; i++) {
        int idx = base + i;
        if (idx < NN) sum += g_deg[idx];
    }
    s[t] = sum;
    __syncthreads();
    for (int off = 1; off < 1024; off <<= 1) {
        int v = (t >= off) ? s[t - off] : 0;
        __syncthreads();
        s[t] += v;
        __syncthreads();
    }
    int run = s[t] - sum;
    for (int i = 0; i < CH; i++) {
        int idx = base + i;
        if (idx < NN) { g_rowptr[idx] = run; run += g_deg[idx]; }
    }
    if (t == 1023) g_rowptr[NN] = s[1023];
}

__global__ void k_fill(const int* __restrict__ dst)
{
    int e = blockIdx.x * blockDim.x + threadIdx.x;
    if (e >= EE) return;
    int d = dst[e];
    int pos = atomicAdd(&g_cursor[d], 1);
    g_eid[g_rowptr[d] + pos] = e;
}

// ---------------- bf16-split conversions ------------------------------------
// A [M,K] fp32 -> A' [M, 3K] bf16 : cols [0,K)=Ah, [K,2K)=Ah, [2K,3K)=Al
__global__ void k_cvtA(const float* __restrict__ src, int K, int total)
{
    int i = blockIdx.x * blockDim.x + threadIdx.x;
    if (i >= total) return;
    int m = i / K, k = i - m * K;
    float v = src[i];
    __nv_bfloat16 h = __float2bfloat16_rn(v);
    __nv_bfloat16 l = __float2bfloat16_rn(v - __bfloat162float(h));
    size_t base = (size_t)m * (3 * K);
    g_A3[base + k] = h;
    g_A3[base + K + k] = h;
    g_A3[base + 2 * K + k] = l;
}

// W [K,256] fp32 -> B' [3K,256] bf16 : rows [0,K)=Bh, [K,2K)=Bl, [2K,3K)=Bh
__global__ void k_cvtW(const float* __restrict__ W, int K)
{
    int i = blockIdx.x * blockDim.x + threadIdx.x;
    if (i >= K * 256) return;
    int k = i >> 8, n = i & 255;
    float v = W[i];
    __nv_bfloat16 h = __float2bfloat16_rn(v);
    __nv_bfloat16 l = __float2bfloat16_rn(v - __bfloat162float(h));
    g_B3[(size_t)k * 256 + n] = h;
    g_B3[(size_t)(K + k) * 256 + n] = l;
    g_B3[(size_t)(2 * K + k) * 256 + n] = h;
}

// ---------------- HMMA GEMM: C[M,256] = A'[M,K'] @ B'[K',256] ---------------
// CTA tile 128x128 (grid.x=2 covers N=256), BK=32, double-buffered cp.async.
#define ASTR 40    // bf16 stride for As rows (padded)
#define BSTR 136   // bf16 stride for Bs rows (padded)

__device__ __forceinline__ void gemm_load(uint32_t as_dst, uint32_t bs_dst,
                                          const __nv_bfloat16* __restrict__ A,
                                          const __nv_bfloat16* __restrict__ B,
                                          int row0, int n0, int k0, int Kp, int tid)
{
#pragma unroll
    for (int c = tid; c < 512; c += 256) {       // A: 128 rows x 64B
        int r = c >> 2, off = c & 3;
        uint32_t d = as_dst + (uint32_t)(r * ASTR + off * 8) * 2;
        const void* s = A + (size_t)(row0 + r) * Kp + k0 + off * 8;
        asm volatile("cp.async.cg.shared.global [%0], [%1], 16;" :: "r"(d), "l"(s));
    }
#pragma unroll
    for (int c = tid; c < 512; c += 256) {       // B: 32 rows x 256B
        int r = c >> 4, off = c & 15;
        uint32_t d = bs_dst + (uint32_t)(r * BSTR + off * 8) * 2;
        const void* s = B + (size_t)(k0 + r) * 256 + n0 + off * 8;
        asm volatile("cp.async.cg.shared.global [%0], [%1], 16;" :: "r"(d), "l"(s));
    }
    asm volatile("cp.async.commit_group;");
}

__global__ void __launch_bounds__(256, 2)
k_gemm_mma(const __nv_bfloat16* __restrict__ A, const __nv_bfloat16* __restrict__ B,
           float* __restrict__ C, int Kp)
{
    __shared__ __align__(16) __nv_bfloat16 As[2][128 * ASTR];
    __shared__ __align__(16) __nv_bfloat16 Bs[2][32 * BSTR];
    int tid = threadIdx.x;
    int wid = tid >> 5, lane = tid & 31;
    int row0 = blockIdx.y * 128;
    int n0 = blockIdx.x * 128;
    int wm = (wid >> 2) * 64;    // warp tile: 64x32
    int wn = (wid & 3) * 32;

    float acc[4][4][4];
#pragma unroll
    for (int i = 0; i < 4; i++)
#pragma unroll
        for (int j = 0; j < 4; j++)
#pragma unroll
            for (int q = 0; q < 4; q++) acc[i][j][q] = 0.f;

    uint32_t asb = smem_u32(As), bsb = smem_u32(Bs);
    const int NIT = Kp >> 5;

    gemm_load(asb, bsb, A, B, row0, n0, 0, Kp, tid);

    for (int it = 0; it < NIT; it++) {
        int buf = it & 1;
        if (it + 1 < NIT) {
            gemm_load(asb + ((it + 1) & 1) * 128 * ASTR * 2,
                      bsb + ((it + 1) & 1) * 32 * BSTR * 2,
                      A, B, row0, n0, (it + 1) * 32, Kp, tid);
            asm volatile("cp.async.wait_group 1;");
        } else {
            asm volatile("cp.async.wait_group 0;");
        }
        __syncthreads();

        uint32_t abuf = asb + buf * 128 * ASTR * 2;
        uint32_t bbuf = bsb + buf * 32 * BSTR * 2;
#pragma unroll
        for (int ks = 0; ks < 32; ks += 16) {
            uint32_t af[4][4];
            int arow = wm + (lane & 7) + ((lane & 8) ? 8 : 0);
            int acol = ks + ((lane & 16) ? 8 : 0);
#pragma unroll
            for (int ms = 0; ms < 4; ms++) {
                uint32_t ad = abuf + (uint32_t)((arow + ms * 16) * ASTR + acol) * 2;
                ldsm_x4(ad, af[ms][0], af[ms][1], af[ms][2], af[ms][3]);
            }
            uint32_t bfr[2][4];
            int bk = ks + ((lane & 8) ? 8 : 0) + (lane & 7);
            int bnl = ((lane & 16) ? 8 : 0);
#pragma unroll
            for (int p = 0; p < 2; p++) {
                uint32_t bd = bbuf + (uint32_t)(bk * BSTR + wn + p * 16 + bnl) * 2;
                ldsm_x4t(bd, bfr[p][0], bfr[p][1], bfr[p][2], bfr[p][3]);
            }
#pragma unroll
            for (int ms = 0; ms < 4; ms++)
#pragma unroll
                for (int ns = 0; ns < 4; ns++) {
                    int p = ns >> 1, q = ns & 1;
                    mma16816(acc[ms][ns], af[ms], bfr[p][q * 2], bfr[p][q * 2 + 1]);
                }
        }
        __syncthreads();
    }

    // epilogue
#pragma unroll
    for (int ms = 0; ms < 4; ms++) {
        int r0 = row0 + wm + ms * 16 + (lane >> 2);
#pragma unroll
        for (int ns = 0; ns < 4; ns++) {
            int cc = n0 + wn + ns * 8 + (lane & 3) * 2;
            if (r0 < NN) {
                C[(size_t)r0 * 256 + cc]     = acc[ms][ns][0];
                C[(size_t)r0 * 256 + cc + 1] = acc[ms][ns][1];
            }
            if (r0 + 8 < NN) {
                C[(size_t)(r0 + 8) * 256 + cc]     = acc[ms][ns][2];
                C[(size_t)(r0 + 8) * 256 + cc + 1] = acc[ms][ns][3];
            }
        }
    }
}

// ---------------- alpha_src / alpha_dst per node ----------------------------
__global__ void k_asad(const float* __restrict__ xh,
                       const float* __restrict__ a_src,
                       const float* __restrict__ a_dst)
{
    int n = blockIdx.x;
    int t = threadIdx.x;  // 256
    float v = xh[n * FDIM + t];
    float ps = v * a_src[t];
    float pd = v * a_dst[t];
#pragma unroll
    for (int off = 16; off > 0; off >>= 1) {
        ps += __shfl_down_sync(0xffffffffu, ps, off);
        pd += __shfl_down_sync(0xffffffffu, pd, off);
    }
    __shared__ float ss[8], sd[8];
    int w = t >> 5, lane = t & 31;
    if (lane == 0) { ss[w] = ps; sd[w] = pd; }
    __syncthreads();
    if (t < HH) {
        g_as[n * HH + t] = ss[2 * t] + ss[2 * t + 1];
        g_ad[n * HH + t] = sd[2 * t] + sd[2 * t + 1];
    }
}

// ---------------- K_h = sum_c W_e[0,h*C+c] * a_e[h,c] ------------------------
__global__ void k_aek(const float* __restrict__ We, const float* __restrict__ ae)
{
    int t = threadIdx.x;  // 256
    float p = We[t] * ae[t];
#pragma unroll
    for (int off = 16; off > 0; off >>= 1)
        p += __shfl_down_sync(0xffffffffu, p, off);
    __shared__ float sh[8];
    int w = t >> 5, lane = t & 31;
    if (lane == 0) sh[w] = p;
    __syncthreads();
    if (t < HH) g_aek[t] = sh[2 * t] + sh[2 * t + 1];
}

// ---------------- per-edge logits ------------------------------------------
__device__ __forceinline__ float lrelu(float x) { return x > 0.f ? x : 0.2f * x; }

__global__ void k_alpha(const int* __restrict__ src, const int* __restrict__ dst,
                        const float* __restrict__ eattr)
{
    int e = blockIdx.x * blockDim.x + threadIdx.x;
    if (e >= EE) return;
    int s = src[e], d = dst[e];
    float ea = eattr[e];
    float4 as = *(const float4*)&g_as[s * 4];
    float4 ad = *(const float4*)&g_ad[d * 4];
    float4 ak = *(const float4*)g_aek;
    float4 a;
    a.x = lrelu(as.x + ad.x + ak.x * ea);
    a.y = lrelu(as.y + ad.y + ak.y * ea);
    a.z = lrelu(as.z + ad.z + ak.z * ea);
    a.w = lrelu(as.w + ad.w + ak.w * ea);
    *(float4*)&g_alpha[e * 4] = a;
}

// ---------------- per-node segment max + sum(exp) (warp per node) ----------
__global__ void k_softmax()
{
    int warp = threadIdx.x >> 5;
    int lane = threadIdx.x & 31;
    int n = blockIdx.x * 4 + warp;
    if (n >= NN) return;
    int lo = g_rowptr[n], hi = g_rowptr[n + 1];
    float4 m = make_float4(-INFINITY, -INFINITY, -INFINITY, -INFINITY);
    for (int i = lo + lane; i < hi; i += 32) {
        int e = g_eid[i];
        float4 a = *(const float4*)&g_alpha[e * 4];
        m.x = fmaxf(m.x, a.x); m.y = fmaxf(m.y, a.y);
        m.z = fmaxf(m.z, a.z); m.w = fmaxf(m.w, a.w);
    }
#pragma unroll
    for (int off = 16; off > 0; off >>= 1) {
        m.x = fmaxf(m.x, __shfl_xor_sync(0xffffffffu, m.x, off));
        m.y = fmaxf(m.y, __shfl_xor_sync(0xffffffffu, m.y, off));
        m.z = fmaxf(m.z, __shfl_xor_sync(0xffffffffu, m.z, off));
        m.w = fmaxf(m.w, __shfl_xor_sync(0xffffffffu, m.w, off));
    }
    float4 s4 = make_float4(0.f, 0.f, 0.f, 0.f);
    for (int i = lo + lane; i < hi; i += 32) {
        int e = g_eid[i];
        float4 a = *(const float4*)&g_alpha[e * 4];
        s4.x += expf(a.x - m.x); s4.y += expf(a.y - m.y);
        s4.z += expf(a.z - m.z); s4.w += expf(a.w - m.w);
    }
#pragma unroll
    for (int off = 16; off > 0; off >>= 1) {
        s4.x += __shfl_xor_sync(0xffffffffu, s4.x, off);
        s4.y += __shfl_xor_sync(0xffffffffu, s4.y, off);
        s4.z += __shfl_xor_sync(0xffffffffu, s4.z, off);
        s4.w += __shfl_xor_sync(0xffffffffu, s4.w, off);
    }
    if (lane == 0) {
        *(float4*)&g_amax[n * 4] = m;
        *(float4*)&g_den[n * 4] = s4;
    }
}

// ---------------- per-edge normalize; emit attention + coeff ----------------
__global__ void k_norm(const int* __restrict__ dst, const float* __restrict__ eatten,
                       float* __restrict__ w_out)
{
    int e = blockIdx.x * blockDim.x + threadIdx.x;
    if (e >= EE) return;
    int d = dst[e];
    float4 a = *(const float4*)&g_alpha[e * 4];
    float4 m = *(const float4*)&g_amax[d * 4];
    float4 dn = *(const float4*)&g_den[d * 4];
    float at = eatten[e];
    float4 w;
    w.x = expf(a.x - m.x) / (dn.x + 1e-16f);
    w.y = expf(a.y - m.y) / (dn.y + 1e-16f);
    w.z = expf(a.z - m.z) / (dn.z + 1e-16f);
    w.w = expf(a.w - m.w) / (dn.w + 1e-16f);
    *(float4*)&w_out[e * 4] = w;
    float4 c = make_float4(w.x * at, w.y * at, w.z * at, w.w * at);
    *(float4*)&g_coeff[e * 4] = c;
}

// ---------------- per-node message aggregation (block per node) -------------
__global__ void k_agg(const int* __restrict__ src, const float* __restrict__ xh,
                      const float* __restrict__ bias, float* __restrict__ out)
{
    int n = blockIdx.x;
    int t = threadIdx.x;     // 256
    int h = t >> 6;
    int lo = g_rowptr[n], hi = g_rowptr[n + 1];
    float acc = 0.f;
    __shared__ int   s_src[64];
    __shared__ float s_c[64][4];
    for (int base = lo; base < hi; base += 64) {
        int cnt = min(64, hi - base);
        if (t < cnt) {
            int e = g_eid[base + t];
            s_src[t] = src[e];
            float4 cc = *(const float4*)&g_coeff[e * 4];
            s_c[t][0] = cc.x; s_c[t][1] = cc.y; s_c[t][2] = cc.z; s_c[t][3] = cc.w;
        }
        __syncthreads();
        for (int i = 0; i < cnt; i++) {
            acc += xh[(long)s_src[i] * FDIM + t] * s_c[i][h];
        }
        __syncthreads();
    }
    out[(long)n * FDIM + t] = acc + bias[t];
}

// ---------------- driver ----------------------------------------------------
extern "C" void kernel_launch(void* const* d_in, const int* in_sizes, int n_in,
                              void* d_out, int out_size)
{
    const float* x      = (const float*)d_in[0];
    const int*   ei     = (const int*)d_in[1];
    const float* eattr  = (const float*)d_in[3];
    const float* eatten = (const float*)d_in[4];
    const float* W1     = (const float*)d_in[5];
    const float* as1    = (const float*)d_in[6];
    const float* ad1    = (const float*)d_in[7];
    const float* We1    = (const float*)d_in[8];
    const float* ae1    = (const float*)d_in[9];
    const float* b1     = (const float*)d_in[10];
    const float* W2     = (const float*)d_in[11];
    const float* as2    = (const float*)d_in[12];
    const float* ad2    = (const float*)d_in[13];
    const float* We2    = (const float*)d_in[14];
    const float* ae2    = (const float*)d_in[15];
    const float* b2     = (const float*)d_in[16];

    const int* src = ei;
    const int* dst = ei + EE;

    float* out    = (float*)d_out;
    float* h_out  = out;
    float* w1_out = out + (long)NN * FDIM;
    float* w2_out = w1_out + (long)EE * HH;

    float* xh = nullptr; float* h1 = nullptr;
    __nv_bfloat16* A3 = nullptr; __nv_bfloat16* B3 = nullptr;
    cudaGetSymbolAddress((void**)&xh, g_xh);
    cudaGetSymbolAddress((void**)&h1, g_h1);
    cudaGetSymbolAddress((void**)&A3, g_A3);
    cudaGetSymbolAddress((void**)&B3, g_B3);

    const int EB = (EE + 255) / 256;
    const dim3 ggrid(2, (NN + 127) / 128);

    // CSR by dst (shared by both layers)
    k_zero<<<(NN + 255) / 256, 256>>>();
    k_deg<<<EB, 256>>>(dst);
    k_scan<<<1, 1024>>>();
    k_fill<<<EB, 256>>>(dst);

    // ---- layer 1 ----
    k_cvtA<<<(NN * 128 + 255) / 256, 256>>>(x, 128, NN * 128);
    k_cvtW<<<(128 * 256 + 255) / 256, 256>>>(W1, 128);
    k_gemm_mma<<<ggrid, 256>>>(A3, B3, xh, 384);
    k_asad<<<NN, 256>>>(xh, as1, ad1);
    k_aek<<<1, 256>>>(We1, ae1);
    k_alpha<<<EB, 256>>>(src, dst, eattr);
    k_softmax<<<(NN + 3) / 4, 128>>>();
    k_norm<<<EB, 256>>>(dst, eatten, w1_out);
    k_agg<<<NN, 256>>>(src, xh, b1, h1);

    // ---- layer 2 ----
    k_cvtA<<<(NN * 256 + 255) / 256, 256>>>(h1, 256, NN * 256);
    k_cvtW<<<(256 * 256 + 255) / 256, 256>>>(W2, 256);
    k_gemm_mma<<<ggrid, 256>>>(A3, B3, xh, 768);
    k_asad<<<NN, 256>>>(xh, as2, ad2);
    k_aek<<<1, 256>>>(We2, ae2);
    k_alpha<<<EB, 256>>>(src, dst, eattr);
    k_softmax<<<(NN + 3) / 4, 128>>>();
    k_norm<<<EB, 256>>>(dst, eatten, w2_out);
    k_agg<<<NN, 256>>>(src, xh, b2, h_out);
}